// round 4
// baseline (speedup 1.0000x reference)
#include <cuda_runtime.h>
#include <cuda_bf16.h>
#include <cstdint>

typedef unsigned long long ull;

#define NB 128
#define NN 1024
#define NT 16          // 64-wide tiles per dim

// Device scratch (no allocs allowed)
__device__ float g_Ut[NN * NN];      // Ut[j][i] = (i<=j) ? W[i][j] : 0     (4 MB)
__device__ float g_V2T[NN * 2 * NB]; // V2T[j][2x] = (V[x][j], V[x][j])     (1 MB)
__device__ float g_VT[NN * NB];      // VT[j][x]  = V[x][j]                 (0.5 MB)
__device__ float g_rc[NN];           // rc[i] = rowsum_i(U) + colsum_i(U)

#define FMA2(d, a, b, c) \
    asm("fma.rn.f32x2 %0, %1, %2, %3;" : "=l"(d) : "l"(a), "l"(b), "l"(c))

__device__ __forceinline__ void unpack2(ull s, float& lo, float& hi) {
    unsigned int a, b;
    asm("mov.b64 {%0, %1}, %2;" : "=r"(a), "=r"(b) : "l"(s));
    lo = __uint_as_float(a);
    hi = __uint_as_float(b);
}

__global__ void zero_rc_kernel() { g_rc[threadIdx.x] = 0.0f; }

// ---- Kernel A: masked transpose of W + rc sums. grid (32,32), block (32,8) ----
__global__ void prep_w_kernel(const float* __restrict__ W) {
    __shared__ float ts[32][33];
    const int tx = threadIdx.x, ty = threadIdx.y;
    const int I0 = blockIdx.y * 32, J0 = blockIdx.x * 32;

    #pragma unroll
    for (int q = 0; q < 4; ++q) {
        int gi = I0 + ty + 8 * q, gj = J0 + tx;
        float w = W[(size_t)gi * NN + gj];            // coalesced
        ts[ty + 8 * q][tx] = (gi <= gj) ? w : 0.0f;
    }
    __syncthreads();
    #pragma unroll
    for (int q = 0; q < 4; ++q) {
        int j = ty + 8 * q;
        g_Ut[(size_t)(J0 + j) * NN + I0 + tx] = ts[tx][j];   // coalesced, smem stride-33
    }
    if (ty == 0) {            // row sums of U (over this j-tile)
        float s = 0.0f;
        #pragma unroll 8
        for (int j = 0; j < 32; ++j) s += ts[tx][j];
        atomicAdd(&g_rc[I0 + tx], s);
    } else if (ty == 1) {     // col sums of U (over this i-tile)
        float s = 0.0f;
        #pragma unroll 8
        for (int i = 0; i < 32; ++i) s += ts[i][tx];
        atomicAdd(&g_rc[J0 + tx], s);
    }
}

// ---- Kernel A2: transpose V into VT and duplicated V2T. grid (32,4), block (32,8) ----
__global__ void prep_v_kernel(const float* __restrict__ V) {
    __shared__ float ts[32][33];
    const int tx = threadIdx.x, ty = threadIdx.y;
    const int X0 = blockIdx.y * 32, J0 = blockIdx.x * 32;

    #pragma unroll
    for (int q = 0; q < 4; ++q)
        ts[ty + 8 * q][tx] = V[(size_t)(X0 + ty + 8 * q) * NN + J0 + tx];  // coalesced
    __syncthreads();
    #pragma unroll
    for (int q = 0; q < 4; ++q) {
        int j = ty + 8 * q;
        float v = ts[tx][j];
        g_VT[(size_t)(J0 + j) * NB + X0 + tx] = v;
        *reinterpret_cast<float2*>(&g_V2T[(size_t)(J0 + j) * (2 * NB) + 2 * (X0 + tx)]) =
            make_float2(v, v);
    }
}

// ---- Kernel C: out[b] = sum_i rc[i]*(0.5 - v[b,i]).  grid 16, block 256 (warp per b) ----
__global__ void init_lin_kernel(const float* __restrict__ V, float* __restrict__ out) {
    const int b    = blockIdx.x * 8 + (threadIdx.x >> 5);
    const int lane = threadIdx.x & 31;
    float e = 0.0f;
    #pragma unroll 8
    for (int q = 0; q < 32; ++q) {
        int i = q * 32 + lane;
        e += g_rc[i] * (0.5f - V[(size_t)b * NN + i]);
    }
    #pragma unroll
    for (int off = 16; off >= 1; off >>= 1)
        e += __shfl_xor_sync(0xffffffffu, e, off);
    if (lane == 0) out[b] = e;
}

// ---- Kernel B: quad term. One block per (upper-tri 64x64 tile, 32-wide j-half). ----
// No smem, no syncs: reads Ut/V2T/VT straight through L1/L2.
__global__ void __launch_bounds__(256, 2)
quad_kernel(float* __restrict__ out) {
    int bid = blockIdx.x;
    int kh  = bid & 1;
    int h   = bid >> 1;
    int ti  = 0;
    while (h >= NT - ti) { h -= NT - ti; ++ti; }
    int tj  = ti + h;

    const int tid = threadIdx.x;
    const int I0 = ti * 64;
    const int J0 = tj * 64 + kh * 32;

    const int ig = tid & 7;          // i-group (8 i's as 4 pairs)
    const int xg = tid >> 3;         // x-group (4 x's)
    const int i0 = ig * 8;
    const int x0 = xg * 4;

    const float* Wp = g_Ut  + (size_t)J0 * NN       + I0 + i0;
    const float* Vp = g_V2T + (size_t)J0 * (2 * NB) + 2 * x0;

    ull acc[4][4];
    #pragma unroll
    for (int p = 0; p < 4; ++p)
        #pragma unroll
        for (int xx = 0; xx < 4; ++xx) acc[p][xx] = 0ull;

    #pragma unroll 4
    for (int k = 0; k < 32; ++k) {
        ulonglong2 wA = *reinterpret_cast<const ulonglong2*>(Wp + (size_t)k * NN);
        ulonglong2 wB = *reinterpret_cast<const ulonglong2*>(Wp + (size_t)k * NN + 4);
        ulonglong2 vA = *reinterpret_cast<const ulonglong2*>(Vp + (size_t)k * (2 * NB));
        ulonglong2 vB = *reinterpret_cast<const ulonglong2*>(Vp + (size_t)k * (2 * NB) + 4);
        const ull w_[4] = {wA.x, wA.y, wB.x, wB.y};   // (w_i, w_i+1) pairs
        const ull v_[4] = {vA.x, vA.y, vB.x, vB.y};   // (v_x, v_x) dups
        #pragma unroll
        for (int p = 0; p < 4; ++p)
            #pragma unroll
            for (int xx = 0; xx < 4; ++xx)
                FMA2(acc[p][xx], w_[p], v_[xx], acc[p][xx]);
    }

    // epilogue: s[x] = sum_i v[x][i] * C[i][x];  VT rows i0..i0+7, cols x0..x0+3
    const float* Xp = g_VT + (size_t)(I0 + i0) * NB + x0;
    float s[4] = {0.0f, 0.0f, 0.0f, 0.0f};
    #pragma unroll
    for (int p = 0; p < 4; ++p) {
        float4 xlo = *reinterpret_cast<const float4*>(Xp + (size_t)(2 * p) * NB);
        float4 xhi = *reinterpret_cast<const float4*>(Xp + (size_t)(2 * p + 1) * NB);
        const float xl[4] = {xlo.x, xlo.y, xlo.z, xlo.w};
        const float xh[4] = {xhi.x, xhi.y, xhi.z, xhi.w};
        #pragma unroll
        for (int xx = 0; xx < 4; ++xx) {
            float alo, ahi;
            unpack2(acc[p][xx], alo, ahi);
            s[xx] += xl[xx] * alo + xh[xx] * ahi;
        }
    }
    #pragma unroll
    for (int off = 4; off >= 1; off >>= 1)
        #pragma unroll
        for (int xx = 0; xx < 4; ++xx)
            s[xx] += __shfl_xor_sync(0xffffffffu, s[xx], off, 8);

    if (ig == 0) {
        #pragma unroll
        for (int xx = 0; xx < 4; ++xx)
            atomicAdd(&out[x0 + xx], 2.0f * s[xx]);   // no return use -> REDG
    }
}

extern "C" void kernel_launch(void* const* d_in, const int* in_sizes, int n_in,
                              void* d_out, int out_size) {
    const float* V = (const float*)d_in[0];   // vector       [128,1024]
    const float* W = (const float*)d_in[1];   // interactions [1024,1024]
    if (n_in >= 2 && in_sizes[0] > in_sizes[1]) {
        V = (const float*)d_in[1];
        W = (const float*)d_in[0];
    }
    float* out = (float*)d_out;

    zero_rc_kernel<<<1, NN>>>();
    prep_w_kernel<<<dim3(32, 32), dim3(32, 8)>>>(W);
    prep_v_kernel<<<dim3(32, 4),  dim3(32, 8)>>>(V);
    init_lin_kernel<<<16, 256>>>(V, out);                 // writes (inits) out
    const int nblocks = (NT * (NT + 1) / 2) * 2;          // 272
    quad_kernel<<<nblocks, 256>>>(out);                   // atomic-adds quad term
}